// round 1
// baseline (speedup 1.0000x reference)
#include <cuda_runtime.h>
#include <math.h>

#define BATCH 4
#define HEADS 16
#define SEQ   1024
#define HD    64
#define DIM   1024
#define ATT_SCALE 0.125f   // HD^-0.5

// Scratch (device globals: allocation-free per harness rules)
__device__ float g_q[BATCH*HEADS*SEQ*HD];   // [b,h,n,d], pre-scaled
__device__ float g_k[BATCH*HEADS*SEQ*HD];
__device__ float g_v[BATCH*HEADS*SEQ*HD];
__device__ float g_att[BATCH*SEQ*DIM];      // [b,n,c] attention output

// ---------------------------------------------------------------------------
// Tiled SIMT fp32 GEMM: C[M,N] = A[M,K] @ B[K,N] + bias
// BM=BN=128, BK=8, 256 threads, 8x8 micro-tile (LDS/FMA balanced on B300).
// MODE 0: plain epilogue, A from param.
// MODE 1: QKV scatter epilogue -> g_q (scaled) / g_k / g_v.
// MODE 2: plain epilogue, A = g_att (avoids host symbol lookup).
// ---------------------------------------------------------------------------
template<int MODE>
__global__ __launch_bounds__(256)
void gemm128(const float* __restrict__ A, const float* __restrict__ Bm,
             const float* __restrict__ bias, float* __restrict__ C,
             int M, int N, int K)
{
    constexpr int BM = 128, BN = 128, BK = 8, TM = 8, TN = 8;
    __shared__ float As[BK][BM + 4];  // [k][row]
    __shared__ float Bs[BK][BN + 4];  // [k][col]

    const float* Ap = (MODE == 2) ? (const float*)g_att : A;

    const int t  = threadIdx.x;
    const int tx = t & 15, ty = t >> 4;
    const int row0 = blockIdx.y * BM, col0 = blockIdx.x * BN;

    // Global load mapping: A tile 128x8 (float4/thread), B tile 8x128 (float4/thread)
    const int ar = t >> 1, ak = (t & 1) * 4;
    const int br = t >> 5, bc = (t & 31) * 4;

    const float* Aptr = Ap + (size_t)(row0 + ar) * K + ak;
    const float* Bptr = Bm + (size_t)br * N + col0 + bc;

    float4 av = *reinterpret_cast<const float4*>(Aptr);
    float4 bv = *reinterpret_cast<const float4*>(Bptr);

    float acc[TM][TN];
    #pragma unroll
    for (int i = 0; i < TM; i++)
        #pragma unroll
        for (int j = 0; j < TN; j++) acc[i][j] = 0.f;

    for (int k0 = 0; k0 < K; k0 += BK) {
        As[ak+0][ar] = av.x; As[ak+1][ar] = av.y;
        As[ak+2][ar] = av.z; As[ak+3][ar] = av.w;
        *reinterpret_cast<float4*>(&Bs[br][bc]) = bv;
        __syncthreads();

        if (k0 + BK < K) {  // prefetch next tiles into registers (overlaps compute)
            av = *reinterpret_cast<const float4*>(Aptr + k0 + BK);
            bv = *reinterpret_cast<const float4*>(Bptr + (size_t)(k0 + BK) * N);
        }

        #pragma unroll
        for (int k = 0; k < BK; ++k) {
            float a[TM], b[TN];
            #pragma unroll
            for (int i = 0; i < TM; i++) a[i] = As[k][ty*TM + i];
            #pragma unroll
            for (int j = 0; j < TN; j++) b[j] = Bs[k][tx*TN + j];
            #pragma unroll
            for (int i = 0; i < TM; i++)
                #pragma unroll
                for (int j = 0; j < TN; j++)
                    acc[i][j] += a[i] * b[j];
        }
        __syncthreads();
    }

    #pragma unroll
    for (int i = 0; i < TM; i++) {
        const int row = row0 + ty*TM + i;
        #pragma unroll
        for (int j = 0; j < TN; j++) {
            const int col = col0 + tx*TN + j;
            float v = acc[i][j] + bias[col];
            if (MODE == 1) {
                const int three = col >> 10;               // which of q/k/v
                const int h  = (col >> 6) & (HEADS - 1);
                const int dd = col & (HD - 1);
                const int b  = row >> 10;
                const int n  = row & (SEQ - 1);
                const size_t idx = (((size_t)(b*HEADS + h))*SEQ + n)*HD + dd;
                if      (three == 0) g_q[idx] = v * ATT_SCALE;
                else if (three == 1) g_k[idx] = v;
                else                 g_v[idx] = v;
            } else {
                C[(size_t)row * N + col] = v;
            }
        }
    }
}

// ---------------------------------------------------------------------------
// Flash attention: grid (SEQ/64, B*H), 256 threads.
// Thread t owns query row r=t/4 and quarter q4=t%4 (16 interleaved cols/dims).
// smem: Q,K,V,P tiles 64x64 fp32, stride 65 (conflict-free) = 65 KB dynamic.
// ---------------------------------------------------------------------------
__global__ __launch_bounds__(256)
void attn_kernel()
{
    extern __shared__ float sm[];
    float* Qs = sm;
    float* Ks = Qs + 64*65;
    float* Vs = Ks + 64*65;
    float* Ps = Vs + 64*65;

    const int t  = threadIdx.x;
    const int r  = t >> 2, q4 = t & 3;
    const int bh = blockIdx.y;
    const int r0 = blockIdx.x * 64;

    const float* Qg = g_q + ((size_t)bh*SEQ + r0)*HD;
    const float* Kg = g_k + (size_t)bh*SEQ*HD;
    const float* Vg = g_v + (size_t)bh*SEQ*HD;

    for (int i = t; i < 64*64; i += 256) {
        const int rr = i >> 6, cc = i & 63;
        Qs[rr*65 + cc] = Qg[(size_t)rr*HD + cc];
    }

    float m = -1e30f, l = 0.f, O[16];
    #pragma unroll
    for (int i = 0; i < 16; i++) O[i] = 0.f;

    for (int j0 = 0; j0 < SEQ; j0 += 64) {
        __syncthreads();  // Q visible (iter 0); prior P/V reads done (iter >0)
        for (int i = t; i < 64*64; i += 256) {
            const int rr = i >> 6, cc = i & 63;
            Ks[rr*65 + cc] = Kg[(size_t)(j0 + rr)*HD + cc];
            Vs[rr*65 + cc] = Vg[(size_t)(j0 + rr)*HD + cc];
        }
        __syncthreads();

        // S tile: thread computes s[c] for c = q4 + 4*i
        float s[16];
        #pragma unroll
        for (int i = 0; i < 16; i++) s[i] = 0.f;
        #pragma unroll 16
        for (int k = 0; k < 64; k++) {
            const float qv = Qs[r*65 + k];
            #pragma unroll
            for (int i = 0; i < 16; i++)
                s[i] += qv * Ks[(q4 + 4*i)*65 + k];
        }

        // online softmax (row stats reduced over the 4 threads of a row)
        float mt = s[0];
        #pragma unroll
        for (int i = 1; i < 16; i++) mt = fmaxf(mt, s[i]);
        mt = fmaxf(mt, __shfl_xor_sync(0xffffffffu, mt, 1));
        mt = fmaxf(mt, __shfl_xor_sync(0xffffffffu, mt, 2));
        const float mnew = fmaxf(m, mt);

        float lt = 0.f;
        #pragma unroll
        for (int i = 0; i < 16; i++) { s[i] = __expf(s[i] - mnew); lt += s[i]; }
        lt += __shfl_xor_sync(0xffffffffu, lt, 1);
        lt += __shfl_xor_sync(0xffffffffu, lt, 2);

        const float alpha = __expf(m - mnew);
        l = l*alpha + lt;
        m = mnew;
        #pragma unroll
        for (int i = 0; i < 16; i++) O[i] *= alpha;

        #pragma unroll
        for (int i = 0; i < 16; i++) Ps[r*65 + q4 + 4*i] = s[i];
        __syncthreads();

        // O += P @ V (thread accumulates dims dd = q4 + 4*i)
        #pragma unroll 8
        for (int c = 0; c < 64; c++) {
            const float pv = Ps[r*65 + c];
            #pragma unroll
            for (int i = 0; i < 16; i++)
                O[i] += pv * Vs[c*65 + q4 + 4*i];
        }
    }

    const float inv = 1.f / l;
    const int b = bh >> 4, h = bh & 15, n = r0 + r;
    float* outp = g_att + ((size_t)b*SEQ + n)*DIM + h*HD;
    #pragma unroll
    for (int i = 0; i < 16; i++) outp[q4 + 4*i] = O[i] * inv;
}

// ---------------------------------------------------------------------------
extern "C" void kernel_launch(void* const* d_in, const int* in_sizes, int n_in,
                              void* d_out, int out_size)
{
    const float* x      = (const float*)d_in[0];
    const float* w_qkv  = (const float*)d_in[1];
    const float* b_qkv  = (const float*)d_in[2];
    const float* w_proj = (const float*)d_in[3];
    const float* b_proj = (const float*)d_in[4];
    float* out = (float*)d_out;

    // 1) QKV GEMM: [4096,1024] @ [1024,3072] -> scatter to g_q/g_k/g_v
    {
        dim3 grid(3*DIM/128, BATCH*SEQ/128);  // (24, 32)
        gemm128<1><<<grid, 256>>>(x, w_qkv, b_qkv, nullptr,
                                  BATCH*SEQ, 3*DIM, DIM);
    }

    // 2) Flash attention -> g_att [B,N,C]
    {
        const size_t smem = (size_t)4 * 64 * 65 * sizeof(float);  // 66560 B
        cudaFuncSetAttribute(attn_kernel,
                             cudaFuncAttributeMaxDynamicSharedMemorySize,
                             (int)smem);
        attn_kernel<<<dim3(SEQ/64, BATCH*HEADS), 256, smem>>>();
    }

    // 3) Projection: g_att @ w_proj + b_proj -> out
    {
        dim3 grid(DIM/128, BATCH*SEQ/128);    // (8, 32)
        gemm128<2><<<grid, 256>>>(nullptr, w_proj, b_proj, out,
                                  BATCH*SEQ, DIM, DIM);
    }
}

// round 2
// speedup vs baseline: 1.3780x; 1.3780x over previous
#include <cuda_runtime.h>
#include <math.h>

#define BATCH 4
#define HEADS 16
#define SEQ   1024
#define HD    64
#define DIM   1024
#define ATT_SCALE 0.125f   // HD^-0.5

// Scratch (device globals: allocation-free per harness rules)
__device__ float g_q[BATCH*HEADS*SEQ*HD];   // [b,h,n,d], pre-scaled
__device__ float g_k[BATCH*HEADS*SEQ*HD];
__device__ float g_v[BATCH*HEADS*SEQ*HD];
__device__ float g_att[BATCH*SEQ*DIM];      // [b,n,c] attention output

// ---------------------------------------------------------------------------
// Tiled SIMT fp32 GEMM: C[M,N] = A[M,K] @ B[K,N] + bias  (unchanged from R1)
// ---------------------------------------------------------------------------
template<int MODE>
__global__ __launch_bounds__(256)
void gemm128(const float* __restrict__ A, const float* __restrict__ Bm,
             const float* __restrict__ bias, float* __restrict__ C,
             int M, int N, int K)
{
    constexpr int BM = 128, BN = 128, BK = 8, TM = 8, TN = 8;
    __shared__ float As[BK][BM + 4];  // [k][row]
    __shared__ float Bs[BK][BN + 4];  // [k][col]

    const float* Ap = (MODE == 2) ? (const float*)g_att : A;

    const int t  = threadIdx.x;
    const int tx = t & 15, ty = t >> 4;
    const int row0 = blockIdx.y * BM, col0 = blockIdx.x * BN;

    const int ar = t >> 1, ak = (t & 1) * 4;
    const int br = t >> 5, bc = (t & 31) * 4;

    const float* Aptr = Ap + (size_t)(row0 + ar) * K + ak;
    const float* Bptr = Bm + (size_t)br * N + col0 + bc;

    float4 av = *reinterpret_cast<const float4*>(Aptr);
    float4 bv = *reinterpret_cast<const float4*>(Bptr);

    float acc[TM][TN];
    #pragma unroll
    for (int i = 0; i < TM; i++)
        #pragma unroll
        for (int j = 0; j < TN; j++) acc[i][j] = 0.f;

    for (int k0 = 0; k0 < K; k0 += BK) {
        As[ak+0][ar] = av.x; As[ak+1][ar] = av.y;
        As[ak+2][ar] = av.z; As[ak+3][ar] = av.w;
        *reinterpret_cast<float4*>(&Bs[br][bc]) = bv;
        __syncthreads();

        if (k0 + BK < K) {
            av = *reinterpret_cast<const float4*>(Aptr + k0 + BK);
            bv = *reinterpret_cast<const float4*>(Bptr + (size_t)(k0 + BK) * N);
        }

        #pragma unroll
        for (int k = 0; k < BK; ++k) {
            float a[TM], b[TN];
            #pragma unroll
            for (int i = 0; i < TM; i++) a[i] = As[k][ty*TM + i];
            #pragma unroll
            for (int j = 0; j < TN; j++) b[j] = Bs[k][tx*TN + j];
            #pragma unroll
            for (int i = 0; i < TM; i++)
                #pragma unroll
                for (int j = 0; j < TN; j++)
                    acc[i][j] += a[i] * b[j];
        }
        __syncthreads();
    }

    #pragma unroll
    for (int i = 0; i < TM; i++) {
        const int row = row0 + ty*TM + i;
        #pragma unroll
        for (int j = 0; j < TN; j++) {
            const int col = col0 + tx*TN + j;
            float v = acc[i][j] + bias[col];
            if (MODE == 1) {
                const int three = col >> 10;
                const int h  = (col >> 6) & (HEADS - 1);
                const int dd = col & (HD - 1);
                const int b  = row >> 10;
                const int n  = row & (SEQ - 1);
                const size_t idx = (((size_t)(b*HEADS + h))*SEQ + n)*HD + dd;
                if      (three == 0) g_q[idx] = v * ATT_SCALE;
                else if (three == 1) g_k[idx] = v;
                else                 g_v[idx] = v;
            } else {
                C[(size_t)row * N + col] = v;
            }
        }
    }
}

// ---------------------------------------------------------------------------
// Flash attention v2: GEMM-style micro-tiles.
// Grid (SEQ/128, B*H), 256 threads. Br=128 q-rows, Bc=128 keys per tile.
// S phase: 8x8 micro (4+4 split rows/cols), float4 smem loads -> 8 LDS.128/64 FMA.
// PV phase: 8x4 micro (rows split 4+4, 4 contiguous dims per thread).
// smem (fp32): Qs[64][132] k-major, Ks[64][132] k-major, Vs[128][68], Ps[128][132].
// Total 169984 B -> 1 CTA/SM, regs up to 255 (no spill).
// ---------------------------------------------------------------------------
#define QS_STR 132
#define KS_STR 132
#define VS_STR 68
#define PS_STR 132

__global__ __launch_bounds__(256)
void attn_kernel()
{
    extern __shared__ float sm[];
    float* Qs = sm;                      // [64 dims][132 rows]
    float* Ks = Qs + 64*QS_STR;          // [64 dims][132 keys]
    float* Vs = Ks + 64*KS_STR;          // [128 keys][68 dims]
    float* Ps = Vs + 128*VS_STR;         // [128 rows][132 keys]

    const int t  = threadIdx.x;
    const int tx = t & 15, ty = t >> 4;  // 16x16 thread grid
    const int bh = blockIdx.y;
    const int r0 = blockIdx.x * 128;

    const float* Qg = g_q + ((size_t)bh*SEQ + r0)*HD;
    const float* Kg = g_k + (size_t)bh*SEQ*HD;
    const float* Vg = g_v + (size_t)bh*SEQ*HD;

    // Load Q tile transposed: Qs[d][r]
    for (int idx = t; idx < 128*64; idx += 256) {
        const int r = idx >> 6, d = idx & 63;
        Qs[d*QS_STR + r] = Qg[(size_t)r*HD + d];
    }

    // Row indices owned by this thread (4+4 split)
    int ri[8];
    #pragma unroll
    for (int i = 0; i < 4; i++) { ri[i] = ty*4 + i; ri[i+4] = 64 + ty*4 + i; }

    float m[8], l[8], O[8][4];
    #pragma unroll
    for (int i = 0; i < 8; i++) {
        m[i] = -1e30f; l[i] = 0.f;
        #pragma unroll
        for (int j = 0; j < 4; j++) O[i][j] = 0.f;
    }

    for (int j0 = 0; j0 < SEQ; j0 += 128) {
        __syncthreads();   // prior PV done reading Vs/Ps (and Q store ordered, iter 0)

        // Load K tile transposed (Ks[d][c]) and V tile natural (Vs[c][d])
        for (int idx = t; idx < 128*64; idx += 256) {
            const int c = idx >> 6, d = idx & 63;
            Ks[d*KS_STR + c] = Kg[(size_t)(j0 + c)*HD + d];
        }
        for (int idx = t; idx < 128*16; idx += 256) {
            const int c = idx >> 4, j = (idx & 15) * 4;
            *reinterpret_cast<float4*>(&Vs[c*VS_STR + j]) =
                *reinterpret_cast<const float4*>(&Vg[(size_t)(j0 + c)*HD + j]);
        }
        __syncthreads();

        // ---- S = Q @ K^T : 8x8 micro-tile ----
        float s[8][8];
        #pragma unroll
        for (int i = 0; i < 8; i++)
            #pragma unroll
            for (int j = 0; j < 8; j++) s[i][j] = 0.f;

        #pragma unroll 4
        for (int k = 0; k < 64; k++) {
            float4 a0 = *reinterpret_cast<const float4*>(&Qs[k*QS_STR + ty*4]);
            float4 a1 = *reinterpret_cast<const float4*>(&Qs[k*QS_STR + 64 + ty*4]);
            float4 b0 = *reinterpret_cast<const float4*>(&Ks[k*KS_STR + tx*4]);
            float4 b1 = *reinterpret_cast<const float4*>(&Ks[k*KS_STR + 64 + tx*4]);
            float a[8] = {a0.x,a0.y,a0.z,a0.w,a1.x,a1.y,a1.z,a1.w};
            float b[8] = {b0.x,b0.y,b0.z,b0.w,b1.x,b1.y,b1.z,b1.w};
            #pragma unroll
            for (int i = 0; i < 8; i++)
                #pragma unroll
                for (int j = 0; j < 8; j++)
                    s[i][j] += a[i] * b[j];
        }

        // ---- Online softmax (per absolute row; 16 lanes share a row) ----
        #pragma unroll
        for (int i = 0; i < 8; i++) {
            float mx = s[i][0];
            #pragma unroll
            for (int j = 1; j < 8; j++) mx = fmaxf(mx, s[i][j]);
            mx = fmaxf(mx, __shfl_xor_sync(0xffffffffu, mx, 1));
            mx = fmaxf(mx, __shfl_xor_sync(0xffffffffu, mx, 2));
            mx = fmaxf(mx, __shfl_xor_sync(0xffffffffu, mx, 4));
            mx = fmaxf(mx, __shfl_xor_sync(0xffffffffu, mx, 8));
            const float mnew = fmaxf(m[i], mx);

            float lt = 0.f;
            #pragma unroll
            for (int j = 0; j < 8; j++) { s[i][j] = __expf(s[i][j] - mnew); lt += s[i][j]; }
            lt += __shfl_xor_sync(0xffffffffu, lt, 1);
            lt += __shfl_xor_sync(0xffffffffu, lt, 2);
            lt += __shfl_xor_sync(0xffffffffu, lt, 4);
            lt += __shfl_xor_sync(0xffffffffu, lt, 8);

            const float alpha = __expf(m[i] - mnew);
            l[i] = l[i]*alpha + lt;
            m[i] = mnew;
            #pragma unroll
            for (int j = 0; j < 4; j++) O[i][j] *= alpha;

            // Store P row fragment (two float4 writes)
            *reinterpret_cast<float4*>(&Ps[ri[i]*PS_STR + tx*4]) =
                make_float4(s[i][0], s[i][1], s[i][2], s[i][3]);
            *reinterpret_cast<float4*>(&Ps[ri[i]*PS_STR + 64 + tx*4]) =
                make_float4(s[i][4], s[i][5], s[i][6], s[i][7]);
        }
        __syncthreads();

        // ---- O += P @ V : 8x4 micro-tile ----
        #pragma unroll 4
        for (int c = 0; c < 128; c++) {
            float4 v = *reinterpret_cast<const float4*>(&Vs[c*VS_STR + tx*4]);
            #pragma unroll
            for (int i = 0; i < 8; i++) {
                const float p = Ps[ri[i]*PS_STR + c];
                O[i][0] += p * v.x;
                O[i][1] += p * v.y;
                O[i][2] += p * v.z;
                O[i][3] += p * v.w;
            }
        }
    }

    // ---- Epilogue ----
    const int b = bh >> 4, h = bh & 15;
    #pragma unroll
    for (int i = 0; i < 8; i++) {
        const float inv = 1.f / l[i];
        const int n = r0 + ri[i];
        float* outp = g_att + ((size_t)b*SEQ + n)*DIM + h*HD + tx*4;
        *reinterpret_cast<float4*>(outp) =
            make_float4(O[i][0]*inv, O[i][1]*inv, O[i][2]*inv, O[i][3]*inv);
    }
}

// ---------------------------------------------------------------------------
extern "C" void kernel_launch(void* const* d_in, const int* in_sizes, int n_in,
                              void* d_out, int out_size)
{
    const float* x      = (const float*)d_in[0];
    const float* w_qkv  = (const float*)d_in[1];
    const float* b_qkv  = (const float*)d_in[2];
    const float* w_proj = (const float*)d_in[3];
    const float* b_proj = (const float*)d_in[4];
    float* out = (float*)d_out;

    // 1) QKV GEMM -> g_q/g_k/g_v
    {
        dim3 grid(3*DIM/128, BATCH*SEQ/128);  // (24, 32)
        gemm128<1><<<grid, 256>>>(x, w_qkv, b_qkv, nullptr,
                                  BATCH*SEQ, 3*DIM, DIM);
    }

    // 2) Flash attention -> g_att
    {
        const size_t smem = (size_t)(64*QS_STR + 64*KS_STR + 128*VS_STR + 128*PS_STR)
                            * sizeof(float);  // 169984 B
        cudaFuncSetAttribute(attn_kernel,
                             cudaFuncAttributeMaxDynamicSharedMemorySize,
                             (int)smem);
        attn_kernel<<<dim3(SEQ/128, BATCH*HEADS), 256, smem>>>();
    }

    // 3) Projection
    {
        dim3 grid(DIM/128, BATCH*SEQ/128);    // (8, 32)
        gemm128<2><<<grid, 256>>>(nullptr, w_proj, b_proj, out,
                                  BATCH*SEQ, DIM, DIM);
    }
}

// round 4
// speedup vs baseline: 2.0648x; 1.4984x over previous
#include <cuda_runtime.h>
#include <cuda_bf16.h>
#include <cstdint>
#include <math.h>

#define BATCH 4
#define HEADS 16
#define SEQ   1024
#define HD    64
#define DIM   1024
#define ATT_SCALE 0.125f   // HD^-0.5

// ---------------------------------------------------------------------------
// Device-global scratch (allocation-free per harness rules)
// ---------------------------------------------------------------------------
__device__ float g_q[BATCH*HEADS*SEQ*HD];
__device__ float g_k[BATCH*HEADS*SEQ*HD];
__device__ float g_v[BATCH*HEADS*SEQ*HD];
__device__ float g_att[BATCH*SEQ*DIM];

__device__ __align__(16) __nv_bfloat16 g_x_hi[BATCH*SEQ*DIM],  g_x_lo[BATCH*SEQ*DIM];
__device__ __align__(16) __nv_bfloat16 g_ah_hi[BATCH*SEQ*DIM], g_ah_lo[BATCH*SEQ*DIM];
__device__ __align__(16) __nv_bfloat16 g_wq_hi[3*DIM*DIM],     g_wq_lo[3*DIM*DIM];  // [N=3072][K=1024]
__device__ __align__(16) __nv_bfloat16 g_wp_hi[DIM*DIM],       g_wp_lo[DIM*DIM];    // [N=1024][K=1024]

// ---------------------------------------------------------------------------
// PTX helpers legal on plain compute_103 (sm_80-era instructions)
// ---------------------------------------------------------------------------
__device__ __forceinline__ uint32_t smem_u32(const void* p) {
    uint32_t a;
    asm("{ .reg .u64 t; cvta.to.shared.u64 t, %1; cvt.u32.u64 %0, t; }" : "=r"(a) : "l"(p));
    return a;
}
__device__ __forceinline__ void cpasync16(uint32_t dst, const void* src) {
    asm volatile("cp.async.cg.shared.global [%0], [%1], 16;" :: "r"(dst), "l"(src));
}
__device__ __forceinline__ void ldsm4(uint32_t* r, uint32_t addr) {
    asm volatile("ldmatrix.sync.aligned.m8n8.x4.shared.b16 {%0,%1,%2,%3}, [%4];"
        : "=r"(r[0]), "=r"(r[1]), "=r"(r[2]), "=r"(r[3]) : "r"(addr));
}
__device__ __forceinline__ void mma16816(float* c, const uint32_t* a, const uint32_t* b) {
    asm volatile(
        "mma.sync.aligned.m16n8k16.row.col.f32.bf16.bf16.f32 "
        "{%0,%1,%2,%3}, {%4,%5,%6,%7}, {%8,%9}, {%0,%1,%2,%3};"
        : "+f"(c[0]), "+f"(c[1]), "+f"(c[2]), "+f"(c[3])
        : "r"(a[0]), "r"(a[1]), "r"(a[2]), "r"(a[3]), "r"(b[0]), "r"(b[1]));
}

// ---------------------------------------------------------------------------
// Prep kernels: fp32 -> bf16 hi/lo split (and transpose for weights)
// ---------------------------------------------------------------------------
template<int SRC>   // 0: x (param), 1: g_att
__global__ void split_bf16(const float* __restrict__ xin, int n4)
{
    const float* src = (SRC == 1) ? (const float*)g_att : xin;
    __nv_bfloat16* dh = (SRC == 1) ? g_ah_hi : g_x_hi;
    __nv_bfloat16* dl = (SRC == 1) ? g_ah_lo : g_x_lo;
    int i = blockIdx.x * blockDim.x + threadIdx.x;
    if (i >= n4) return;
    float4 v = reinterpret_cast<const float4*>(src)[i];
    __nv_bfloat16 h0 = __float2bfloat16_rn(v.x), h1 = __float2bfloat16_rn(v.y);
    __nv_bfloat16 h2 = __float2bfloat16_rn(v.z), h3 = __float2bfloat16_rn(v.w);
    __nv_bfloat16 l0 = __float2bfloat16_rn(v.x - __bfloat162float(h0));
    __nv_bfloat16 l1 = __float2bfloat16_rn(v.y - __bfloat162float(h1));
    __nv_bfloat16 l2 = __float2bfloat16_rn(v.z - __bfloat162float(h2));
    __nv_bfloat16 l3 = __float2bfloat16_rn(v.w - __bfloat162float(h3));
    __nv_bfloat162* ph = reinterpret_cast<__nv_bfloat162*>(dh) + i*2;
    __nv_bfloat162* pl = reinterpret_cast<__nv_bfloat162*>(dl) + i*2;
    ph[0] = __nv_bfloat162(h0, h1); ph[1] = __nv_bfloat162(h2, h3);
    pl[0] = __nv_bfloat162(l0, l1); pl[1] = __nv_bfloat162(l2, l3);
}

template<int W>     // 0: w_qkv [1024][3072], 1: w_proj [1024][1024]
__global__ void transpose_split(const float* __restrict__ src)
{
    constexpr int R = DIM;
    constexpr int C = (W == 0) ? 3*DIM : DIM;
    __nv_bfloat16* dh = (W == 0) ? g_wq_hi : g_wp_hi;
    __nv_bfloat16* dl = (W == 0) ? g_wq_lo : g_wp_lo;
    __shared__ float tile[32][33];
    const int c0 = blockIdx.x * 32, r0 = blockIdx.y * 32;
    const int x = threadIdx.x, y = threadIdx.y;  // 32 x 8
    #pragma unroll
    for (int i = 0; i < 32; i += 8)
        tile[y + i][x] = src[(size_t)(r0 + y + i) * C + c0 + x];
    __syncthreads();
    #pragma unroll
    for (int i = 0; i < 32; i += 8) {
        float v = tile[x][y + i];                    // = src[r0+x][c0+y+i]
        __nv_bfloat16 h = __float2bfloat16_rn(v);
        __nv_bfloat16 l = __float2bfloat16_rn(v - __bfloat162float(h));
        const size_t o = (size_t)(c0 + y + i) * R + r0 + x;
        dh[o] = h; dl[o] = l;
    }
}

// ---------------------------------------------------------------------------
// HMMA bf16-split GEMM: C[M,N] = Ahi/lo[M,K] @ (Bhi/lo[N,K])^T + bias
// Tile 128x128, BK=32, 256 thr (8 warps, 32x64 warp tiles), double-buffered
// cp.async, smem stride 40 halves (80B: ldmatrix conflict-free).
// MODE 1: QKV scatter epilogue. MODE 2: plain (proj).
// ---------------------------------------------------------------------------
#define T_STR    40                      // halves per smem row
#define TILE_B   (128*T_STR*2)           // 10240 B per 128x32 bf16 tile
#define OFF_AH   0
#define OFF_AL   (TILE_B)
#define OFF_BH   (2*TILE_B)
#define OFF_BL   (3*TILE_B)
#define STAGE_B  (4*TILE_B)              // 40960 B
#define NSTAGE   (DIM/32)                // 32 k-chunks

template<int MODE>
__global__ __launch_bounds__(256, 2)
void mma_gemm(const float* __restrict__ bias, float* __restrict__ Cout, int N)
{
    constexpr int K = 1024;
    extern __shared__ char smem[];
    const uint32_t sb = smem_u32(smem);

    const int t = threadIdx.x, wid = t >> 5, lane = t & 31;
    const int wr = wid & 3, wc = wid >> 2;       // 4x2 warp grid
    const int lp = lane & 15, lq = lane >> 4;
    const int m0 = blockIdx.y * 128, n0 = blockIdx.x * 128;

    const __nv_bfloat16* Ah = (MODE == 1) ? g_x_hi : g_ah_hi;
    const __nv_bfloat16* Al = (MODE == 1) ? g_x_lo : g_ah_lo;
    const __nv_bfloat16* Bh = (MODE == 1) ? g_wq_hi : g_wp_hi;
    const __nv_bfloat16* Bl = (MODE == 1) ? g_wq_lo : g_wp_lo;

    const __nv_bfloat16* aH = Ah + (size_t)m0 * K;
    const __nv_bfloat16* aL = Al + (size_t)m0 * K;
    const __nv_bfloat16* bH = Bh + (size_t)n0 * K;
    const __nv_bfloat16* bL = Bl + (size_t)n0 * K;

    // ldmatrix base offsets (bytes) within a tile
    const uint32_t arow = (uint32_t)((wr*32 + lp) * 80 + lq * 16);
    const uint32_t brow = (uint32_t)((wc*64 + lp) * 80 + lq * 16);

    float acc[2][8][4];
    #pragma unroll
    for (int i = 0; i < 2; i++)
        #pragma unroll
        for (int j = 0; j < 8; j++)
            #pragma unroll
            for (int q = 0; q < 4; q++) acc[i][j][q] = 0.f;

    // loader: fill stage buf with k-chunk ks
    auto load_stage = [&](int buf, int ks) {
        const uint32_t st = sb + buf * STAGE_B;
        const int k0h = ks * 32;
        #pragma unroll
        for (int rep = 0; rep < 2; rep++) {
            const int idx = t + rep * 256;       // 0..511
            const int r = idx >> 2, s = idx & 3;
            const uint32_t so = (uint32_t)(r * 80 + s * 16);
            const size_t go = (size_t)r * K + k0h + s * 8;
            cpasync16(st + OFF_AH + so, aH + go);
            cpasync16(st + OFF_AL + so, aL + go);
            cpasync16(st + OFF_BH + so, bH + go);
            cpasync16(st + OFF_BL + so, bL + go);
        }
        asm volatile("cp.async.commit_group;" ::: "memory");
    };

    load_stage(0, 0);

    for (int ks = 0; ks < NSTAGE; ks++) {
        if (ks + 1 < NSTAGE) {
            load_stage((ks + 1) & 1, ks + 1);
            asm volatile("cp.async.wait_group 1;" ::: "memory");
        } else {
            asm volatile("cp.async.wait_group 0;" ::: "memory");
        }
        __syncthreads();

        const uint32_t st = sb + (ks & 1) * STAGE_B;
        #pragma unroll
        for (int kk = 0; kk < 2; kk++) {
            const uint32_t kb = kk * 32;  // 16 halves = 32 B
            uint32_t bh[4][4], bl[4][4];
            #pragma unroll
            for (int ng = 0; ng < 4; ng++) {
                ldsm4(bh[ng], st + OFF_BH + brow + ng*1280 + kb);
                ldsm4(bl[ng], st + OFF_BL + brow + ng*1280 + kb);
            }
            #pragma unroll
            for (int rg = 0; rg < 2; rg++) {
                uint32_t ah[4], al[4];
                ldsm4(ah, st + OFF_AH + arow + rg*1280 + kb);
                ldsm4(al, st + OFF_AL + arow + rg*1280 + kb);
                #pragma unroll
                for (int ng = 0; ng < 4; ng++) {
                    uint32_t b0h[2] = {bh[ng][0], bh[ng][2]};
                    uint32_t b1h[2] = {bh[ng][1], bh[ng][3]};
                    uint32_t b0l[2] = {bl[ng][0], bl[ng][2]};
                    uint32_t b1l[2] = {bl[ng][1], bl[ng][3]};
                    mma16816(acc[rg][2*ng],   ah, b0h);
                    mma16816(acc[rg][2*ng],   al, b0h);
                    mma16816(acc[rg][2*ng],   ah, b0l);
                    mma16816(acc[rg][2*ng+1], ah, b1h);
                    mma16816(acc[rg][2*ng+1], al, b1h);
                    mma16816(acc[rg][2*ng+1], ah, b1l);
                }
            }
        }
        __syncthreads();
    }

    // ---- Epilogue ----
    const int gcb = n0 + wc*64;        // warp col base (64-aligned -> one head)
    const int lrow = lane >> 2, lc2 = 2*(lane & 3);

    if (MODE == 1) {
        const int three = gcb >> 10;
        const int h     = (gcb >> 6) & (HEADS - 1);
        float* base = (three == 0 ? g_q : three == 1 ? g_k : g_v);
        const float sc = (three == 0) ? ATT_SCALE : 1.0f;
        #pragma unroll
        for (int rg = 0; rg < 2; rg++) {
            const int row = m0 + wr*32 + rg*16 + lrow;
            const int b = row >> 10, n = row & (SEQ - 1);
            float* dst0 = base + (((size_t)(b*HEADS + h))*SEQ + n)*HD;
            float* dst1 = base + (((size_t)(b*HEADS + h))*SEQ + (n + 8))*HD;  // row+8 same b (128-tile)
            #pragma unroll
            for (int ng = 0; ng < 4; ng++)
                #pragma unroll
                for (int j = 0; j < 2; j++) {
                    const int col = gcb + ng*16 + j*8 + lc2;
                    const int dd = col & 63;
                    const float b0 = bias[col], b1 = bias[col + 1];
                    float* c = acc[rg][2*ng + j];
                    *reinterpret_cast<float2*>(dst0 + dd) =
                        make_float2((c[0] + b0) * sc, (c[1] + b1) * sc);
                    *reinterpret_cast<float2*>(dst1 + dd) =
                        make_float2((c[2] + b0) * sc, (c[3] + b1) * sc);
                }
        }
    } else {
        #pragma unroll
        for (int rg = 0; rg < 2; rg++) {
            const int row = m0 + wr*32 + rg*16 + lrow;
            float* dst0 = Cout + (size_t)row * N;
            float* dst1 = Cout + (size_t)(row + 8) * N;
            #pragma unroll
            for (int ng = 0; ng < 4; ng++)
                #pragma unroll
                for (int j = 0; j < 2; j++) {
                    const int col = gcb + ng*16 + j*8 + lc2;
                    const float b0 = bias[col], b1 = bias[col + 1];
                    float* c = acc[rg][2*ng + j];
                    *reinterpret_cast<float2*>(dst0 + col) = make_float2(c[0] + b0, c[1] + b1);
                    *reinterpret_cast<float2*>(dst1 + col) = make_float2(c[2] + b0, c[3] + b1);
                }
        }
    }
}

// ---------------------------------------------------------------------------
// Flash attention (unchanged from R2): GEMM-style micro-tiles, fp32 SIMT.
// ---------------------------------------------------------------------------
#define QS_STR 132
#define KS_STR 132
#define VS_STR 68
#define PS_STR 132

__global__ __launch_bounds__(256)
void attn_kernel()
{
    extern __shared__ float sm[];
    float* Qs = sm;
    float* Ks = Qs + 64*QS_STR;
    float* Vs = Ks + 64*KS_STR;
    float* Ps = Vs + 128*VS_STR;

    const int t  = threadIdx.x;
    const int tx = t & 15, ty = t >> 4;
    const int bh = blockIdx.y;
    const int r0 = blockIdx.x * 128;

    const float* Qg = g_q + ((size_t)bh*SEQ + r0)*HD;
    const float* Kg = g_k + (size_t)bh*SEQ*HD;
    const float* Vg = g_v + (size_t)bh*SEQ*HD;

    for (int idx = t; idx < 128*64; idx += 256) {
        const int r = idx >> 6, d = idx & 63;
        Qs[d*QS_STR + r] = Qg[(size_t)r*HD + d];
    }

    int ri[8];
    #pragma unroll
    for (int i = 0; i < 4; i++) { ri[i] = ty*4 + i; ri[i+4] = 64 + ty*4 + i; }

    float m[8], l[8], O[8][4];
    #pragma unroll
    for (int i = 0; i < 8; i++) {
        m[i] = -1e30f; l[i] = 0.f;
        #pragma unroll
        for (int j = 0; j < 4; j++) O[i][j] = 0.f;
    }

    for (int j0 = 0; j0 < SEQ; j0 += 128) {
        __syncthreads();
        for (int idx = t; idx < 128*64; idx += 256) {
            const int c = idx >> 6, d = idx & 63;
            Ks[d*KS_STR + c] = Kg[(size_t)(j0 + c)*HD + d];
        }
        for (int idx = t; idx < 128*16; idx += 256) {
            const int c = idx >> 4, j = (idx & 15) * 4;
            *reinterpret_cast<float4*>(&Vs[c*VS_STR + j]) =
                *reinterpret_cast<const float4*>(&Vg[(size_t)(j0 + c)*HD + j]);
        }
        __syncthreads();

        float s[8][8];
        #pragma unroll
        for (int i = 0; i < 8; i++)
            #pragma unroll
            for (int j = 0; j < 8; j++) s[i][j] = 0.f;

        #pragma unroll 4
        for (int k = 0; k < 64; k++) {
            float4 a0 = *reinterpret_cast<const float4*>(&Qs[k*QS_STR + ty*4]);
            float4 a1 = *reinterpret_cast<const float4*>(&Qs[k*QS_STR + 64 + ty*4]);
            float4 b0 = *reinterpret_cast<const float4*>(&Ks[k*KS_STR + tx*4]);
            float4 b1 = *reinterpret_cast<const float4*>(&Ks[k*KS_STR + 64 + tx*4]);
            float a[8] = {a0.x,a0.y,a0.z,a0.w,a1.x,a1.y,a1.z,a1.w};
            float b[8] = {b0.x,b0.y,b0.z,b0.w,b1.x,b1.y,b1.z,b1.w};
            #pragma unroll
            for (int i = 0; i < 8; i++)
                #pragma unroll
                for (int j = 0; j < 8; j++)
                    s[i][j] += a[i] * b[j];
        }

        #pragma unroll
        for (int i = 0; i < 8; i++) {
            float mx = s[i][0];
            #pragma unroll
            for (int j = 1; j < 8; j++) mx = fmaxf(mx, s[i][j]);
            mx = fmaxf(mx, __shfl_xor_sync(0xffffffffu, mx, 1));
            mx = fmaxf(mx, __shfl_xor_sync(0xffffffffu, mx, 2));
            mx = fmaxf(mx, __shfl_xor_sync(0xffffffffu, mx, 4));
            mx = fmaxf(mx, __shfl_xor_sync(0xffffffffu, mx, 8));
            const float mnew = fmaxf(m[i], mx);

            float lt = 0.f;
            #pragma unroll
            for (int j = 0; j < 8; j++) { s[i][j] = __expf(s[i][j] - mnew); lt += s[i][j]; }
            lt += __shfl_xor_sync(0xffffffffu, lt, 1);
            lt += __shfl_xor_sync(0xffffffffu, lt, 2);
            lt += __shfl_xor_sync(0xffffffffu, lt, 4);
            lt += __shfl_xor_sync(0xffffffffu, lt, 8);

            const float alpha = __expf(m[i] - mnew);
            l[i] = l[i]*alpha + lt;
            m[i] = mnew;
            #pragma unroll
            for (int j = 0; j < 4; j++) O[i][j] *= alpha;

            *reinterpret_cast<float4*>(&Ps[ri[i]*PS_STR + tx*4]) =
                make_float4(s[i][0], s[i][1], s[i][2], s[i][3]);
            *reinterpret_cast<float4*>(&Ps[ri[i]*PS_STR + 64 + tx*4]) =
                make_float4(s[i][4], s[i][5], s[i][6], s[i][7]);
        }
        __syncthreads();

        #pragma unroll 4
        for (int c = 0; c < 128; c++) {
            float4 v = *reinterpret_cast<const float4*>(&Vs[c*VS_STR + tx*4]);
            #pragma unroll
            for (int i = 0; i < 8; i++) {
                const float p = Ps[ri[i]*PS_STR + c];
                O[i][0] += p * v.x;
                O[i][1] += p * v.y;
                O[i][2] += p * v.z;
                O[i][3] += p * v.w;
            }
        }
    }

    const int b = bh >> 4, h = bh & 15;
    #pragma unroll
    for (int i = 0; i < 8; i++) {
        const float inv = 1.f / l[i];
        const int n = r0 + ri[i];
        float* outp = g_att + ((size_t)b*SEQ + n)*DIM + h*HD + tx*4;
        *reinterpret_cast<float4*>(outp) =
            make_float4(O[i][0]*inv, O[i][1]*inv, O[i][2]*inv, O[i][3]*inv);
    }
}

// ---------------------------------------------------------------------------
extern "C" void kernel_launch(void* const* d_in, const int* in_sizes, int n_in,
                              void* d_out, int out_size)
{
    const float* x      = (const float*)d_in[0];
    const float* w_qkv  = (const float*)d_in[1];
    const float* b_qkv  = (const float*)d_in[2];
    const float* w_proj = (const float*)d_in[3];
    const float* b_proj = (const float*)d_in[4];
    float* out = (float*)d_out;

    const int gemm_smem = 2 * STAGE_B;   // 81920 B
    cudaFuncSetAttribute(mma_gemm<1>, cudaFuncAttributeMaxDynamicSharedMemorySize, gemm_smem);
    cudaFuncSetAttribute(mma_gemm<2>, cudaFuncAttributeMaxDynamicSharedMemorySize, gemm_smem);

    // 0) Prep: split x, split+transpose weights
    split_bf16<0><<<4096, 256>>>(x, BATCH*SEQ*DIM/4);
    transpose_split<0><<<dim3(96, 32), dim3(32, 8)>>>(w_qkv);
    transpose_split<1><<<dim3(32, 32), dim3(32, 8)>>>(w_proj);

    // 1) QKV GEMM (HMMA bf16-split) -> scatter g_q/g_k/g_v
    mma_gemm<1><<<dim3(3*DIM/128, BATCH*SEQ/128), 256, gemm_smem>>>(b_qkv, nullptr, 3*DIM);

    // 2) Flash attention -> g_att
    {
        const size_t smem = (size_t)(64*QS_STR + 64*KS_STR + 128*VS_STR + 128*PS_STR)
                            * sizeof(float);  // 169984 B
        cudaFuncSetAttribute(attn_kernel,
                             cudaFuncAttributeMaxDynamicSharedMemorySize, (int)smem);
        attn_kernel<<<dim3(SEQ/128, BATCH*HEADS), 256, smem>>>();
    }

    // 3) Split attention output, projection GEMM (HMMA)
    split_bf16<1><<<4096, 256>>>(nullptr, BATCH*SEQ*DIM/4);
    mma_gemm<2><<<dim3(DIM/128, BATCH*SEQ/128), 256, gemm_smem>>>(b_proj, out, DIM);
}

// round 6
// speedup vs baseline: 3.4218x; 1.6572x over previous
#include <cuda_runtime.h>
#include <cuda_bf16.h>
#include <cstdint>
#include <math.h>

#define BATCH 4
#define HEADS 16
#define SEQ   1024
#define HD    64
#define DIM   1024
#define ATT_SCALE 0.125f   // HD^-0.5

// ---------------------------------------------------------------------------
// Device-global scratch (allocation-free per harness rules)
// ---------------------------------------------------------------------------
__device__ __align__(16) __nv_bfloat16 g_qh[BATCH*HEADS*SEQ*HD], g_ql[BATCH*HEADS*SEQ*HD];
__device__ __align__(16) __nv_bfloat16 g_kh[BATCH*HEADS*SEQ*HD], g_kl[BATCH*HEADS*SEQ*HD];
__device__ __align__(16) __nv_bfloat16 g_vh[BATCH*HEADS*SEQ*HD], g_vl[BATCH*HEADS*SEQ*HD];

__device__ __align__(16) __nv_bfloat16 g_x_hi[BATCH*SEQ*DIM],  g_x_lo[BATCH*SEQ*DIM];
__device__ __align__(16) __nv_bfloat16 g_ah_hi[BATCH*SEQ*DIM], g_ah_lo[BATCH*SEQ*DIM];
__device__ __align__(16) __nv_bfloat16 g_wq_hi[3*DIM*DIM],     g_wq_lo[3*DIM*DIM];  // [N=3072][K=1024]
__device__ __align__(16) __nv_bfloat16 g_wp_hi[DIM*DIM],       g_wp_lo[DIM*DIM];    // [N=1024][K=1024]

// ---------------------------------------------------------------------------
// PTX helpers legal on plain compute_103 (sm_80-era instructions)
// ---------------------------------------------------------------------------
__device__ __forceinline__ uint32_t smem_u32(const void* p) {
    uint32_t a;
    asm("{ .reg .u64 t; cvta.to.shared.u64 t, %1; cvt.u32.u64 %0, t; }" : "=r"(a) : "l"(p));
    return a;
}
__device__ __forceinline__ void cpasync16(uint32_t dst, const void* src) {
    asm volatile("cp.async.cg.shared.global [%0], [%1], 16;" :: "r"(dst), "l"(src));
}
__device__ __forceinline__ void ldsm4(uint32_t* r, uint32_t addr) {
    asm volatile("ldmatrix.sync.aligned.m8n8.x4.shared.b16 {%0,%1,%2,%3}, [%4];"
        : "=r"(r[0]), "=r"(r[1]), "=r"(r[2]), "=r"(r[3]) : "r"(addr));
}
__device__ __forceinline__ void ldsm4t(uint32_t* r, uint32_t addr) {
    asm volatile("ldmatrix.sync.aligned.m8n8.x4.trans.shared.b16 {%0,%1,%2,%3}, [%4];"
        : "=r"(r[0]), "=r"(r[1]), "=r"(r[2]), "=r"(r[3]) : "r"(addr));
}
__device__ __forceinline__ void mma16816(float* c, const uint32_t* a, const uint32_t* b) {
    asm volatile(
        "mma.sync.aligned.m16n8k16.row.col.f32.bf16.bf16.f32 "
        "{%0,%1,%2,%3}, {%4,%5,%6,%7}, {%8,%9}, {%0,%1,%2,%3};"
        : "+f"(c[0]), "+f"(c[1]), "+f"(c[2]), "+f"(c[3])
        : "r"(a[0]), "r"(a[1]), "r"(a[2]), "r"(a[3]), "r"(b[0]), "r"(b[1]));
}
// pack two floats into bf16x2 hi + bf16x2 lo (residual)
__device__ __forceinline__ void split2(float x, float y, uint32_t& hi, uint32_t& lo) {
    __nv_bfloat16 hx = __float2bfloat16_rn(x), hy = __float2bfloat16_rn(y);
    __nv_bfloat16 lx = __float2bfloat16_rn(x - __bfloat162float(hx));
    __nv_bfloat16 ly = __float2bfloat16_rn(y - __bfloat162float(hy));
    __nv_bfloat162 H(hx, hy), L(lx, ly);
    hi = *reinterpret_cast<uint32_t*>(&H);
    lo = *reinterpret_cast<uint32_t*>(&L);
}

// ---------------------------------------------------------------------------
// Prep kernels
// ---------------------------------------------------------------------------
__global__ void split_x(const float* __restrict__ src, int n4)
{
    int i = blockIdx.x * blockDim.x + threadIdx.x;
    if (i >= n4) return;
    float4 v = reinterpret_cast<const float4*>(src)[i];
    uint32_t h0, l0, h1, l1;
    split2(v.x, v.y, h0, l0);
    split2(v.z, v.w, h1, l1);
    uint32_t* ph = reinterpret_cast<uint32_t*>(g_x_hi) + i*2;
    uint32_t* pl = reinterpret_cast<uint32_t*>(g_x_lo) + i*2;
    ph[0] = h0; ph[1] = h1; pl[0] = l0; pl[1] = l1;
}

template<int W>     // 0: w_qkv [1024][3072], 1: w_proj [1024][1024]
__global__ void transpose_split(const float* __restrict__ src)
{
    constexpr int R = DIM;
    constexpr int C = (W == 0) ? 3*DIM : DIM;
    __nv_bfloat16* dh = (W == 0) ? g_wq_hi : g_wp_hi;
    __nv_bfloat16* dl = (W == 0) ? g_wq_lo : g_wp_lo;
    __shared__ float tile[32][33];
    const int c0 = blockIdx.x * 32, r0 = blockIdx.y * 32;
    const int x = threadIdx.x, y = threadIdx.y;  // 32 x 8
    #pragma unroll
    for (int i = 0; i < 32; i += 8)
        tile[y + i][x] = src[(size_t)(r0 + y + i) * C + c0 + x];
    __syncthreads();
    #pragma unroll
    for (int i = 0; i < 32; i += 8) {
        float v = tile[x][y + i];
        __nv_bfloat16 h = __float2bfloat16_rn(v);
        __nv_bfloat16 l = __float2bfloat16_rn(v - __bfloat162float(h));
        const size_t o = (size_t)(c0 + y + i) * R + r0 + x;
        dh[o] = h; dl[o] = l;
    }
}

// ---------------------------------------------------------------------------
// HMMA bf16-split GEMM.  MODE 1: QKV epilogue -> bf16 hi/lo Q/K/V.
// MODE 2: plain fp32 epilogue (proj).
// ---------------------------------------------------------------------------
#define T_STR    40
#define TILE_B   (128*T_STR*2)
#define OFF_AH   0
#define OFF_AL   (TILE_B)
#define OFF_BH   (2*TILE_B)
#define OFF_BL   (3*TILE_B)
#define STAGE_B  (4*TILE_B)
#define NSTAGE   (DIM/32)

template<int MODE>
__global__ __launch_bounds__(256, 2)
void mma_gemm(const float* __restrict__ bias, float* __restrict__ Cout, int N)
{
    constexpr int K = 1024;
    extern __shared__ char smem[];
    const uint32_t sb = smem_u32(smem);

    const int t = threadIdx.x, wid = t >> 5, lane = t & 31;
    const int wr = wid & 3, wc = wid >> 2;
    const int lp = lane & 15, lq = lane >> 4;
    const int m0 = blockIdx.y * 128, n0 = blockIdx.x * 128;

    const __nv_bfloat16* Ah = (MODE == 1) ? g_x_hi : g_ah_hi;
    const __nv_bfloat16* Al = (MODE == 1) ? g_x_lo : g_ah_lo;
    const __nv_bfloat16* Bh = (MODE == 1) ? g_wq_hi : g_wp_hi;
    const __nv_bfloat16* Bl = (MODE == 1) ? g_wq_lo : g_wp_lo;

    const __nv_bfloat16* aH = Ah + (size_t)m0 * K;
    const __nv_bfloat16* aL = Al + (size_t)m0 * K;
    const __nv_bfloat16* bH = Bh + (size_t)n0 * K;
    const __nv_bfloat16* bL = Bl + (size_t)n0 * K;

    const uint32_t arow = (uint32_t)((wr*32 + lp) * 80 + lq * 16);
    const uint32_t brow = (uint32_t)((wc*64 + lp) * 80 + lq * 16);

    float acc[2][8][4];
    #pragma unroll
    for (int i = 0; i < 2; i++)
        #pragma unroll
        for (int j = 0; j < 8; j++)
            #pragma unroll
            for (int q = 0; q < 4; q++) acc[i][j][q] = 0.f;

    auto load_stage = [&](int buf, int ks) {
        const uint32_t st = sb + buf * STAGE_B;
        const int k0h = ks * 32;
        #pragma unroll
        for (int rep = 0; rep < 2; rep++) {
            const int idx = t + rep * 256;
            const int r = idx >> 2, s = idx & 3;
            const uint32_t so = (uint32_t)(r * 80 + s * 16);
            const size_t go = (size_t)r * K + k0h + s * 8;
            cpasync16(st + OFF_AH + so, aH + go);
            cpasync16(st + OFF_AL + so, aL + go);
            cpasync16(st + OFF_BH + so, bH + go);
            cpasync16(st + OFF_BL + so, bL + go);
        }
        asm volatile("cp.async.commit_group;" ::: "memory");
    };

    load_stage(0, 0);

    for (int ks = 0; ks < NSTAGE; ks++) {
        if (ks + 1 < NSTAGE) {
            load_stage((ks + 1) & 1, ks + 1);
            asm volatile("cp.async.wait_group 1;" ::: "memory");
        } else {
            asm volatile("cp.async.wait_group 0;" ::: "memory");
        }
        __syncthreads();

        const uint32_t st = sb + (ks & 1) * STAGE_B;
        #pragma unroll
        for (int kk = 0; kk < 2; kk++) {
            const uint32_t kb = kk * 32;
            uint32_t bh[4][4], bl[4][4];
            #pragma unroll
            for (int ng = 0; ng < 4; ng++) {
                ldsm4(bh[ng], st + OFF_BH + brow + ng*1280 + kb);
                ldsm4(bl[ng], st + OFF_BL + brow + ng*1280 + kb);
            }
            #pragma unroll
            for (int rg = 0; rg < 2; rg++) {
                uint32_t ah[4], al[4];
                ldsm4(ah, st + OFF_AH + arow + rg*1280 + kb);
                ldsm4(al, st + OFF_AL + arow + rg*1280 + kb);
                #pragma unroll
                for (int ng = 0; ng < 4; ng++) {
                    uint32_t b0h[2] = {bh[ng][0], bh[ng][2]};
                    uint32_t b1h[2] = {bh[ng][1], bh[ng][3]};
                    uint32_t b0l[2] = {bl[ng][0], bl[ng][2]};
                    uint32_t b1l[2] = {bl[ng][1], bl[ng][3]};
                    mma16816(acc[rg][2*ng],   ah, b0h);
                    mma16816(acc[rg][2*ng],   al, b0h);
                    mma16816(acc[rg][2*ng],   ah, b0l);
                    mma16816(acc[rg][2*ng+1], ah, b1h);
                    mma16816(acc[rg][2*ng+1], al, b1h);
                    mma16816(acc[rg][2*ng+1], ah, b1l);
                }
            }
        }
        __syncthreads();
    }

    // ---- Epilogue ----
    const int gcb = n0 + wc*64;       // 64-aligned -> single head / single q|k|v
    const int lrow = lane >> 2, lc2 = 2*(lane & 3);

    if (MODE == 1) {
        const int three = gcb >> 10;
        const int h     = (gcb >> 6) & (HEADS - 1);
        __nv_bfloat16* dsth = (three == 0) ? g_qh : (three == 1) ? g_kh : g_vh;
        __nv_bfloat16* dstl = (three == 0) ? g_ql : (three == 1) ? g_kl : g_vl;
        const float sc = (three == 0) ? ATT_SCALE : 1.0f;
        #pragma unroll
        for (int rg = 0; rg < 2; rg++) {
            const int row = m0 + wr*32 + rg*16 + lrow;
            const int b = row >> 10, n = row & (SEQ - 1);
            const size_t r0i = (((size_t)(b*HEADS + h))*SEQ + n)*HD;
            const size_t r1i = r0i + (size_t)8*HD;
            #pragma unroll
            for (int ng = 0; ng < 4; ng++)
                #pragma unroll
                for (int j = 0; j < 2; j++) {
                    const int col = gcb + ng*16 + j*8 + lc2;
                    const int dd = col & 63;
                    const float b0 = bias[col], b1 = bias[col + 1];
                    float* c = acc[rg][2*ng + j];
                    uint32_t h01, l01, h23, l23;
                    split2((c[0] + b0) * sc, (c[1] + b1) * sc, h01, l01);
                    split2((c[2] + b0) * sc, (c[3] + b1) * sc, h23, l23);
                    *reinterpret_cast<uint32_t*>(dsth + r0i + dd) = h01;
                    *reinterpret_cast<uint32_t*>(dstl + r0i + dd) = l01;
                    *reinterpret_cast<uint32_t*>(dsth + r1i + dd) = h23;
                    *reinterpret_cast<uint32_t*>(dstl + r1i + dd) = l23;
                }
        }
    } else {
        #pragma unroll
        for (int rg = 0; rg < 2; rg++) {
            const int row = m0 + wr*32 + rg*16 + lrow;
            float* dst0 = Cout + (size_t)row * N;
            float* dst1 = Cout + (size_t)(row + 8) * N;
            #pragma unroll
            for (int ng = 0; ng < 4; ng++)
                #pragma unroll
                for (int j = 0; j < 2; j++) {
                    const int col = gcb + ng*16 + j*8 + lc2;
                    const float b0 = bias[col], b1 = bias[col + 1];
                    float* c = acc[rg][2*ng + j];
                    *reinterpret_cast<float2*>(dst0 + col) = make_float2(c[0] + b0, c[1] + b1);
                    *reinterpret_cast<float2*>(dst1 + col) = make_float2(c[2] + b0, c[3] + b1);
                }
        }
    }
}

// ---------------------------------------------------------------------------
// Flash attention, HMMA bf16 hi/lo split.
// Grid (SEQ/128, B*H), 256 thr (8 warps x m16 rows). Bc=64 keys/iter.
// smem: Qh/Ql [128][72], per stage Kh/Kl/Vh/Vl [64][72]; double buffered.
// Writes output directly as bf16 hi/lo into g_ah_hi / g_ah_lo.
// ---------------------------------------------------------------------------
#define AT_T     72                        // halves per smem row (144 B)
#define AT_QH    0
#define AT_QL    18432
#define AT_STG   36864                     // first KV stage
#define AT_STGB  36864                     // stage size
#define AT_KL    9216
#define AT_VH    18432
#define AT_VL    27648
#define AT_SMEM  (AT_STG + 2*AT_STGB)      // 110592 B

__global__ __launch_bounds__(256, 2)
void attn_mma()
{
    extern __shared__ char smem[];
    const uint32_t sb = smem_u32(smem);
    const int t = threadIdx.x, lane = t & 31, wid = t >> 5;
    const int bh = blockIdx.y;
    const int r0 = blockIdx.x * 128;
    const size_t bho = (size_t)bh * SEQ * HD;

    const __nv_bfloat16* Qh = g_qh + bho + (size_t)r0 * HD;
    const __nv_bfloat16* Ql = g_ql + bho + (size_t)r0 * HD;
    const __nv_bfloat16* Kh = g_kh + bho;
    const __nv_bfloat16* Kl = g_kl + bho;
    const __nv_bfloat16* Vh = g_vh + bho;
    const __nv_bfloat16* Vl = g_vl + bho;

    // Q tiles (once): 128 rows x 8 segs x {hi,lo} = 2048 cp.async transfers
    for (int i = t; i < 2048; i += 256) {
        const int tile = i >> 10, rem = i & 1023, row = rem >> 3, seg = rem & 7;
        const __nv_bfloat16* src = (tile ? Ql : Qh) + (size_t)row * HD + seg * 8;
        cpasync16(sb + (tile ? AT_QL : AT_QH) + row*144 + seg*16, src);
    }
    auto load_stage = [&](int buf, int j0) {
        const uint32_t st = sb + AT_STG + buf * AT_STGB;
        for (int i = t; i < 2048; i += 256) {
            const int tile = i >> 9, rem = i & 511, row = rem >> 3, seg = rem & 7;
            const __nv_bfloat16* src =
                (tile == 0 ? Kh : tile == 1 ? Kl : tile == 2 ? Vh : Vl)
                + (size_t)(j0 + row) * HD + seg * 8;
            cpasync16(st + tile*9216 + row*144 + seg*16, src);
        }
        asm volatile("cp.async.commit_group;" ::: "memory");
    };
    load_stage(0, 0);   // commits Q too

    // ldmatrix per-thread offsets (bytes)
    const int mrow = lane & 7, mid = lane >> 3;
    const uint32_t qoff = (uint32_t)(((wid*16 + ((mid & 1) ? 8 : 0) + mrow) * AT_T
                                      + ((mid & 2) ? 8 : 0)) * 2);
    const uint32_t koff = (uint32_t)(((((mid & 2) ? 8 : 0) + mrow) * AT_T
                                      + ((mid & 1) ? 8 : 0)) * 2);
    const uint32_t voff = (uint32_t)(((((mid & 1) ? 8 : 0) + mrow) * AT_T
                                      + ((mid & 2) ? 8 : 0)) * 2);

    float o[8][4];
    #pragma unroll
    for (int i = 0; i < 8; i++)
        #pragma unroll
        for (int q = 0; q < 4; q++) o[i][q] = 0.f;
    float mA = -1e30f, mB = -1e30f, lA = 0.f, lB = 0.f;

    for (int it = 0; it < SEQ/64; it++) {
        if (it + 1 < SEQ/64) {
            load_stage((it + 1) & 1, (it + 1) * 64);
            asm volatile("cp.async.wait_group 1;" ::: "memory");
        } else {
            asm volatile("cp.async.wait_group 0;" ::: "memory");
        }
        __syncthreads();

        const uint32_t KHb = sb + AT_STG + (it & 1) * AT_STGB;
        const uint32_t KLb = KHb + AT_KL, VHb = KHb + AT_VH, VLb = KHb + AT_VL;

        // ---- S = Q K^T (split) ----
        float s[8][4];
        #pragma unroll
        for (int i = 0; i < 8; i++)
            #pragma unroll
            for (int q = 0; q < 4; q++) s[i][q] = 0.f;

        #pragma unroll
        for (int g = 0; g < 4; g++) {
            uint32_t qfh[4], qfl[4];
            ldsm4(qfh, sb + AT_QH + qoff + g*32);
            ldsm4(qfl, sb + AT_QL + qoff + g*32);
            #pragma unroll
            for (int j = 0; j < 4; j++) {
                uint32_t kh[4], kl[4];
                const uint32_t off = koff + (uint32_t)((j*16*AT_T + g*16) * 2);
                ldsm4(kh, KHb + off);
                ldsm4(kl, KLb + off);
                uint32_t b0h[2] = {kh[0], kh[1]}, b1h[2] = {kh[2], kh[3]};
                uint32_t b0l[2] = {kl[0], kl[1]}, b1l[2] = {kl[2], kl[3]};
                mma16816(s[2*j],   qfh, b0h);
                mma16816(s[2*j],   qfl, b0h);
                mma16816(s[2*j],   qfh, b0l);
                mma16816(s[2*j+1], qfh, b1h);
                mma16816(s[2*j+1], qfl, b1h);
                mma16816(s[2*j+1], qfh, b1l);
            }
        }

        // ---- online softmax (rows: A = lane/4, B = lane/4 + 8) ----
        float mxA = s[0][0], mxB = s[0][2];
        #pragma unroll
        for (int i = 0; i < 8; i++) {
            mxA = fmaxf(mxA, fmaxf(s[i][0], s[i][1]));
            mxB = fmaxf(mxB, fmaxf(s[i][2], s[i][3]));
        }
        mxA = fmaxf(mxA, __shfl_xor_sync(0xffffffffu, mxA, 1));
        mxA = fmaxf(mxA, __shfl_xor_sync(0xffffffffu, mxA, 2));
        mxB = fmaxf(mxB, __shfl_xor_sync(0xffffffffu, mxB, 1));
        mxB = fmaxf(mxB, __shfl_xor_sync(0xffffffffu, mxB, 2));
        const float nmA = fmaxf(mA, mxA), nmB = fmaxf(mB, mxB);

        float ltA = 0.f, ltB = 0.f;
        #pragma unroll
        for (int i = 0; i < 8; i++) {
            s[i][0] = __expf(s[i][0] - nmA); ltA += s[i][0];
            s[i][1] = __expf(s[i][1] - nmA); ltA += s[i][1];
            s[i][2] = __expf(s[i][2] - nmB); ltB += s[i][2];
            s[i][3] = __expf(s[i][3] - nmB); ltB += s[i][3];
        }
        ltA += __shfl_xor_sync(0xffffffffu, ltA, 1);
        ltA += __shfl_xor_sync(0xffffffffu, ltA, 2);
        ltB += __shfl_xor_sync(0xffffffffu, ltB, 1);
        ltB += __shfl_xor_sync(0xffffffffu, ltB, 2);

        const float aA = __expf(mA - nmA), aB = __expf(mB - nmB);
        lA = lA * aA + ltA;  mA = nmA;
        lB = lB * aB + ltB;  mB = nmB;
        #pragma unroll
        for (int i = 0; i < 8; i++) {
            o[i][0] *= aA; o[i][1] *= aA;
            o[i][2] *= aB; o[i][3] *= aB;
        }

        // ---- O += P V (split; P C-frag == A-frag layout) ----
        #pragma unroll
        for (int g = 0; g < 4; g++) {
            uint32_t ph[4], pl[4];
            split2(s[2*g][0],   s[2*g][1],   ph[0], pl[0]);
            split2(s[2*g][2],   s[2*g][3],   ph[1], pl[1]);
            split2(s[2*g+1][0], s[2*g+1][1], ph[2], pl[2]);
            split2(s[2*g+1][2], s[2*g+1][3], ph[3], pl[3]);
            #pragma unroll
            for (int j = 0; j < 4; j++) {
                uint32_t vh[4], vl[4];
                const uint32_t off = voff + (uint32_t)((g*16*AT_T + j*16) * 2);
                ldsm4t(vh, VHb + off);
                ldsm4t(vl, VLb + off);
                uint32_t b0h[2] = {vh[0], vh[1]}, b1h[2] = {vh[2], vh[3]};
                uint32_t b0l[2] = {vl[0], vl[1]}, b1l[2] = {vl[2], vl[3]};
                mma16816(o[2*j],   ph, b0h);
                mma16816(o[2*j],   pl, b0h);
                mma16816(o[2*j],   ph, b0l);
                mma16816(o[2*j+1], ph, b1h);
                mma16816(o[2*j+1], pl, b1h);
                mma16816(o[2*j+1], ph, b1l);
            }
        }
        __syncthreads();
    }

    // ---- epilogue: write bf16 hi/lo attention output ----
    const float iA = 1.f / lA, iB = 1.f / lB;
    const int b = bh >> 4, h = bh & 15;
    const int nA = r0 + wid*16 + (lane >> 2), nB = nA + 8;
    const size_t baseA = ((size_t)(b*SEQ + nA))*DIM + h*HD;
    const size_t baseB = ((size_t)(b*SEQ + nB))*DIM + h*HD;
    #pragma unroll
    for (int tt = 0; tt < 8; tt++) {
        const int d = tt*8 + 2*(lane & 3);
        uint32_t hA, lAo, hB, lBo;
        split2(o[tt][0]*iA, o[tt][1]*iA, hA, lAo);
        split2(o[tt][2]*iB, o[tt][3]*iB, hB, lBo);
        *reinterpret_cast<uint32_t*>(g_ah_hi + baseA + d) = hA;
        *reinterpret_cast<uint32_t*>(g_ah_lo + baseA + d) = lAo;
        *reinterpret_cast<uint32_t*>(g_ah_hi + baseB + d) = hB;
        *reinterpret_cast<uint32_t*>(g_ah_lo + baseB + d) = lBo;
    }
}

// ---------------------------------------------------------------------------
extern "C" void kernel_launch(void* const* d_in, const int* in_sizes, int n_in,
                              void* d_out, int out_size)
{
    const float* x      = (const float*)d_in[0];
    const float* w_qkv  = (const float*)d_in[1];
    const float* b_qkv  = (const float*)d_in[2];
    const float* w_proj = (const float*)d_in[3];
    const float* b_proj = (const float*)d_in[4];
    float* out = (float*)d_out;

    const int gemm_smem = 2 * STAGE_B;   // 81920 B
    cudaFuncSetAttribute(mma_gemm<1>, cudaFuncAttributeMaxDynamicSharedMemorySize, gemm_smem);
    cudaFuncSetAttribute(mma_gemm<2>, cudaFuncAttributeMaxDynamicSharedMemorySize, gemm_smem);
    cudaFuncSetAttribute(attn_mma,    cudaFuncAttributeMaxDynamicSharedMemorySize, AT_SMEM);

    // 0) Prep: split x, split+transpose weights
    split_x<<<4096, 256>>>(x, BATCH*SEQ*DIM/4);
    transpose_split<0><<<dim3(96, 32), dim3(32, 8)>>>(w_qkv);
    transpose_split<1><<<dim3(32, 32), dim3(32, 8)>>>(w_proj);

    // 1) QKV GEMM -> bf16 hi/lo Q/K/V (Q pre-scaled)
    mma_gemm<1><<<dim3(3*DIM/128, BATCH*SEQ/128), 256, gemm_smem>>>(b_qkv, nullptr, 3*DIM);

    // 2) Flash attention (HMMA split) -> bf16 hi/lo g_ah
    attn_mma<<<dim3(SEQ/128, BATCH*HEADS), 256, AT_SMEM>>>();

    // 3) Projection GEMM
    mma_gemm<2><<<dim3(DIM/128, BATCH*SEQ/128), 256, gemm_smem>>>(b_proj, out, DIM);
}